// round 17
// baseline (speedup 1.0000x reference)
#include <cuda_runtime.h>
#include <cuda_bf16.h>
#include <cuda_fp16.h>
#include <cstdint>

#define NN 50000
#define DEG 16

#define TSTRIDE 136
#define TBYTES (128 * TSTRIDE * 2)   // one 128x128 padded bf16 tile = 34816 B
#define WM_SMEM (6 * TBYTES)         // Ahi|Alo|B0hi|B0lo|B1hi|B1lo = 208896 B
#define TC_SMEM (3 * TBYTES)         // Ahi|Alo|Bbuf = 104448 B -> 2 CTAs/SM

// Scratch
__device__ float g_A[(size_t)NN * 128];    // x @ Wm_top (fp32)
__device__ uint4 g_bx[(size_t)NN * 32];    // packed per node: [B fp16 x4 | x fp16 x4]
__device__ uint2 g_xnh[(size_t)NN * 32];   // x_new fp16
__device__ float g_g[(size_t)NN * 128];    // segment_sum(adj * x_new[src])

// ───────────────── tensor-core helpers (sm_80 baseline PTX) ─────────────────
__device__ __forceinline__ uint32_t smem_u32(const void* p) {
    uint32_t a;
    asm("{ .reg .u64 t; cvta.to.shared.u64 t, %1; cvt.u32.u64 %0, t; }"
        : "=r"(a) : "l"(p));
    return a;
}
__device__ __forceinline__ void ldsm_x4(uint32_t& r0, uint32_t& r1,
                                        uint32_t& r2, uint32_t& r3,
                                        uint32_t addr) {
    asm volatile("ldmatrix.sync.aligned.m8n8.x4.shared.b16 {%0,%1,%2,%3}, [%4];"
                 : "=r"(r0), "=r"(r1), "=r"(r2), "=r"(r3) : "r"(addr));
}
__device__ __forceinline__ void mma_bf16(float* c, const uint32_t* a,
                                         const uint32_t* b) {
    asm volatile(
        "mma.sync.aligned.m16n8k16.row.col.f32.bf16.bf16.f32 "
        "{%0,%1,%2,%3}, {%4,%5,%6,%7}, {%8,%9}, {%0,%1,%2,%3};"
        : "+f"(c[0]), "+f"(c[1]), "+f"(c[2]), "+f"(c[3])
        : "r"(a[0]), "r"(a[1]), "r"(a[2]), "r"(a[3]), "r"(b[0]), "r"(b[1]));
}

// split-convert 2 floats -> packed bf16x2 hi + packed bf16x2 lo (RN)
__device__ __forceinline__ void cvt2(float vx, float vy, uint32_t& hi, uint32_t& lo) {
    uint32_t p;
    asm("cvt.rn.bf16x2.f32 %0, %1, %2;" : "=r"(p) : "f"(vy), "f"(vx));
    const float fx = __uint_as_float(p << 16);
    const float fy = __uint_as_float(p & 0xffff0000u);
    uint32_t q;
    asm("cvt.rn.bf16x2.f32 %0, %1, %2;" : "=r"(q) : "f"(vy - fy), "f"(vx - fx));
    hi = p; lo = q;
}
// hi-only convert (packed), and lo given the packed hi
__device__ __forceinline__ uint32_t cvt_hi(float vx, float vy) {
    uint32_t p;
    asm("cvt.rn.bf16x2.f32 %0, %1, %2;" : "=r"(p) : "f"(vy), "f"(vx));
    return p;
}
__device__ __forceinline__ uint32_t cvt_lo(float vx, float vy, uint32_t p) {
    const float fx = __uint_as_float(p << 16);
    const float fy = __uint_as_float(p & 0xffff0000u);
    uint32_t q;
    asm("cvt.rn.bf16x2.f32 %0, %1, %2;" : "=r"(q) : "f"(vy - fy), "f"(vx - fx));
    return q;
}

// ===========================================================================
// wm_merged_k: one CTA (512 thr, 16 warps) computes BOTH Wm halves for a
// 128-row tile: A-convert once, mma over N=256.
//   matrix 0 output -> g_A fp32 (+ pack x fp16 into g_bx)
//   matrix 1 output -> packed B fp16 into g_bx
// ===========================================================================
__global__ __launch_bounds__(512, 1) void wm_merged_k(
    const float* __restrict__ X, const float* __restrict__ wm, int M)
{
    extern __shared__ char sh[];
    __nv_bfloat16* Ahi = (__nv_bfloat16*)(sh);
    __nv_bfloat16* Alo = (__nv_bfloat16*)(sh + TBYTES);

    const int tid  = threadIdx.x;
    const int lane = tid & 31;
    const int wid  = tid >> 5;
    const int row0 = blockIdx.x * 128;

    if (tid < 256) {
        // A: thread t -> row t>>1, k-half (t&1)*64 (+ pack x fp16)
        const int r  = tid >> 1;
        const int kh = (tid & 1) * 64;
        const bool valid = (row0 + r) < M;
        const float4* Xr = (const float4*)(X + (size_t)(row0 + r) * 128 + kh);
#pragma unroll
        for (int kk = 0; kk < 64; kk += 4) {
            float4 v = valid ? Xr[kk >> 2] : make_float4(0.f, 0.f, 0.f, 0.f);
            uint32_t h01, l01, h23, l23;
            cvt2(v.x, v.y, h01, l01);
            cvt2(v.z, v.w, h23, l23);
            const int k = kh + kk;
            *(uint2*)&Ahi[r * TSTRIDE + k] = make_uint2(h01, h23);
            *(uint2*)&Alo[r * TSTRIDE + k] = make_uint2(l01, l23);
            if (valid) {
                __half2 x01 = __floats2half2_rn(v.x, v.y);
                __half2 x23 = __floats2half2_rn(v.z, v.w);
                *(uint2*)((char*)&g_bx[(size_t)(row0 + r) * 32 + (k >> 2)] + 8) =
                    make_uint2(*(uint32_t*)&x01, *(uint32_t*)&x23);
            }
        }
    } else {
        // W: thread t2 -> matrix m = t2>>7, column n = t2&127 (coalesced reads)
        const int t2 = tid - 256;
        const int m = t2 >> 7, n = t2 & 127;
        const float* src = wm + (size_t)m * 128 * 128;
        __nv_bfloat16* Bh = (__nv_bfloat16*)(sh + 2 * TBYTES + m * 2 * TBYTES);
        __nv_bfloat16* Bl = (__nv_bfloat16*)((char*)Bh + TBYTES);
#pragma unroll 4
        for (int k = 0; k < 128; k += 4) {
            const float v0 = src[(k + 0) * 128 + n], v1 = src[(k + 1) * 128 + n];
            const float v2 = src[(k + 2) * 128 + n], v3 = src[(k + 3) * 128 + n];
            uint32_t h01, l01, h23, l23;
            cvt2(v0, v1, h01, l01);
            cvt2(v2, v3, h23, l23);
            *(uint2*)&Bh[n * TSTRIDE + k] = make_uint2(h01, h23);
            *(uint2*)&Bl[n * TSTRIDE + k] = make_uint2(l01, l23);
        }
    }
    __syncthreads();

    // ---- mainloop: 16 warps, warp tile 32(M) x 64(N) over 128x256 ----
    const int mr  = (wid & 3) * 32;
    const int nc  = (wid >> 2) * 64;     // 0..192
    const int m   = nc >> 7;             // output matrix
    const int ncl = nc & 127;

    float acc[2][8][4];
#pragma unroll
    for (int tm = 0; tm < 2; tm++)
#pragma unroll
        for (int j = 0; j < 8; j++)
#pragma unroll
            for (int q = 0; q < 4; q++) acc[tm][j][q] = 0.f;

    const uint32_t sb = smem_u32(sh);
    const uint32_t a_lane = ((lane & 15) * TSTRIDE + (lane >> 4) * 8) * 2;
    const uint32_t sA[2] = { sb + (uint32_t)(mr * TSTRIDE * 2) + a_lane,
                             sb + (uint32_t)((mr + 16) * TSTRIDE * 2) + a_lane };
    const uint32_t bbase = sb + 2 * TBYTES + (uint32_t)(m * 2 * TBYTES);
    const uint32_t sB[4] = { bbase + (uint32_t)(ncl * TSTRIDE * 2) + a_lane,
                             bbase + (uint32_t)((ncl + 16) * TSTRIDE * 2) + a_lane,
                             bbase + (uint32_t)((ncl + 32) * TSTRIDE * 2) + a_lane,
                             bbase + (uint32_t)((ncl + 48) * TSTRIDE * 2) + a_lane };

    const uint32_t aoff[3] = { 0u, 0u, (uint32_t)TBYTES };
    const uint32_t boff[3] = { 0u, (uint32_t)TBYTES, 0u };

#pragma unroll 1
    for (int p = 0; p < 3; p++) {
#pragma unroll
        for (int kk = 0; kk < 8; kk++) {
            const uint32_t kb = kk * 32;
            uint32_t a[2][4];
            ldsm_x4(a[0][0], a[0][1], a[0][2], a[0][3], sA[0] + aoff[p] + kb);
            ldsm_x4(a[1][0], a[1][1], a[1][2], a[1][3], sA[1] + aoff[p] + kb);
            uint32_t b[8][2];
#pragma unroll
            for (int jp = 0; jp < 4; jp++) {
                uint32_t m0, m1, m2, m3;
                ldsm_x4(m0, m1, m2, m3, sB[jp] + boff[p] + kb);
                b[2 * jp][0] = m0; b[2 * jp][1] = m2;
                b[2 * jp + 1][0] = m1; b[2 * jp + 1][1] = m3;
            }
#pragma unroll
            for (int tm = 0; tm < 2; tm++)
#pragma unroll
                for (int j = 0; j < 8; j++)
                    mma_bf16(acc[tm][j], a[tm], b[j]);
        }
    }

    // ---- epilogue ----
#pragma unroll
    for (int j = 0; j < 8; j++) {
        const int col = ncl + j * 8 + (lane & 3) * 2;
#pragma unroll
        for (int tm = 0; tm < 2; tm++) {
            const int ra = row0 + mr + tm * 16 + (lane >> 2);
            const int rb = ra + 8;
            if (m == 0) {
                if (ra < M)
                    *(float2*)(g_A + (size_t)ra * 128 + col) =
                        make_float2(acc[tm][j][0], acc[tm][j][1]);
                if (rb < M)
                    *(float2*)(g_A + (size_t)rb * 128 + col) =
                        make_float2(acc[tm][j][2], acc[tm][j][3]);
            } else {
                const uint32_t off = (uint32_t)((col >> 2) * 16 + (col & 3) * 2);
                if (ra < M) {
                    __half2 h = __floats2half2_rn(acc[tm][j][0], acc[tm][j][1]);
                    *(uint32_t*)((char*)&g_bx[(size_t)ra * 32] + off) = *(uint32_t*)&h;
                }
                if (rb < M) {
                    __half2 h = __floats2half2_rn(acc[tm][j][2], acc[tm][j][3]);
                    *(uint32_t*)((char*)&g_bx[(size_t)rb * 32] + off) = *(uint32_t*)&h;
                }
            }
        }
    }
}

// ===========================================================================
// tc_gemm_k: out = g_g @ weight + bias. Single-resident-B variant:
// smem = Ahi|Alo|Bbuf (104.4 KB) -> 2 CTAs/SM. Pass order:
//   p0: Ahi*Bhi, p1: Alo*Bhi, p2: Ahi*Blo (Bbuf reloaded with Blo before p2).
// ===========================================================================
__global__ __launch_bounds__(256, 2) void tc_gemm_k(
    const float* __restrict__ X, const float* __restrict__ W,
    const float* __restrict__ bias, float* __restrict__ C, int M)
{
    extern __shared__ char sh[];
    __nv_bfloat16* Ahi = (__nv_bfloat16*)(sh);
    __nv_bfloat16* Alo = (__nv_bfloat16*)(sh + TBYTES);
    __nv_bfloat16* Bbuf = (__nv_bfloat16*)(sh + 2 * TBYTES);

    const int tid  = threadIdx.x;
    const int lane = tid & 31;
    const int wid  = tid >> 5;
    const int row0 = blockIdx.x * 128;

    if (tid < 128) {
        const int r = tid;
        const bool valid = (row0 + r) < M;
        const float4* Xr = (const float4*)(X + (size_t)(row0 + r) * 128);
#pragma unroll 8
        for (int k = 0; k < 128; k += 4) {
            float4 v = valid ? Xr[k >> 2] : make_float4(0.f, 0.f, 0.f, 0.f);
            uint32_t h01, l01, h23, l23;
            cvt2(v.x, v.y, h01, l01);
            cvt2(v.z, v.w, h23, l23);
            *(uint2*)&Ahi[r * TSTRIDE + k] = make_uint2(h01, h23);
            *(uint2*)&Alo[r * TSTRIDE + k] = make_uint2(l01, l23);
        }
    } else {
        const int n = tid - 128;
#pragma unroll 4
        for (int k = 0; k < 128; k += 4) {
            const float v0 = W[(k + 0) * 128 + n], v1 = W[(k + 1) * 128 + n];
            const float v2 = W[(k + 2) * 128 + n], v3 = W[(k + 3) * 128 + n];
            *(uint2*)&Bbuf[n * TSTRIDE + k] =
                make_uint2(cvt_hi(v0, v1), cvt_hi(v2, v3));
        }
    }
    __syncthreads();

    const int mr = (wid & 3) * 32;
    const int nc = (wid >> 2) * 64;

    float acc[2][8][4];
#pragma unroll
    for (int tm = 0; tm < 2; tm++)
#pragma unroll
        for (int j = 0; j < 8; j++)
#pragma unroll
            for (int q = 0; q < 4; q++) acc[tm][j][q] = 0.f;

    const uint32_t sb = smem_u32(sh);
    const uint32_t a_lane = ((lane & 15) * TSTRIDE + (lane >> 4) * 8) * 2;
    const uint32_t sA[2] = { sb + (uint32_t)(mr * TSTRIDE * 2) + a_lane,
                             sb + (uint32_t)((mr + 16) * TSTRIDE * 2) + a_lane };
    const uint32_t bbase = sb + 2 * TBYTES;
    const uint32_t sB[4] = { bbase + (uint32_t)(nc * TSTRIDE * 2) + a_lane,
                             bbase + (uint32_t)((nc + 16) * TSTRIDE * 2) + a_lane,
                             bbase + (uint32_t)((nc + 32) * TSTRIDE * 2) + a_lane,
                             bbase + (uint32_t)((nc + 48) * TSTRIDE * 2) + a_lane };

    // p0: Ahi*Bhi, p1: Alo*Bhi, p2: Ahi*Blo
    const uint32_t aoff[3] = { 0u, (uint32_t)TBYTES, 0u };

#pragma unroll 1
    for (int p = 0; p < 3; p++) {
        if (p == 2) {
            __syncthreads();   // all warps finished reading Bhi
            if (tid >= 128) {  // recompute Blo into Bbuf (W is L1/L2-hot)
                const int n = tid - 128;
#pragma unroll 4
                for (int k = 0; k < 128; k += 4) {
                    const float v0 = W[(k + 0) * 128 + n], v1 = W[(k + 1) * 128 + n];
                    const float v2 = W[(k + 2) * 128 + n], v3 = W[(k + 3) * 128 + n];
                    const uint32_t h01 = cvt_hi(v0, v1), h23 = cvt_hi(v2, v3);
                    *(uint2*)&Bbuf[n * TSTRIDE + k] =
                        make_uint2(cvt_lo(v0, v1, h01), cvt_lo(v2, v3, h23));
                }
            }
            __syncthreads();
        }
#pragma unroll
        for (int kk = 0; kk < 8; kk++) {
            const uint32_t kb = kk * 32;
            uint32_t a[2][4];
            ldsm_x4(a[0][0], a[0][1], a[0][2], a[0][3], sA[0] + aoff[p] + kb);
            ldsm_x4(a[1][0], a[1][1], a[1][2], a[1][3], sA[1] + aoff[p] + kb);
            uint32_t b[8][2];
#pragma unroll
            for (int jp = 0; jp < 4; jp++) {
                uint32_t m0, m1, m2, m3;
                ldsm_x4(m0, m1, m2, m3, sB[jp] + kb);
                b[2 * jp][0] = m0; b[2 * jp][1] = m2;
                b[2 * jp + 1][0] = m1; b[2 * jp + 1][1] = m3;
            }
#pragma unroll
            for (int tm = 0; tm < 2; tm++)
#pragma unroll
                for (int j = 0; j < 8; j++)
                    mma_bf16(acc[tm][j], a[tm], b[j]);
        }
    }

#pragma unroll
    for (int j = 0; j < 8; j++) {
        const int col = nc + j * 8 + (lane & 3) * 2;
        const float2 bv = *(const float2*)(bias + col);
#pragma unroll
        for (int tm = 0; tm < 2; tm++) {
            const int ra = row0 + mr + tm * 16 + (lane >> 2);
            const int rb = ra + 8;
            if (ra < M)
                *(float2*)(C + (size_t)ra * 128 + col) =
                    make_float2(acc[tm][j][0] + bv.x, acc[tm][j][1] + bv.y);
            if (rb < M)
                *(float2*)(C + (size_t)rb * 128 + col) =
                    make_float2(acc[tm][j][2] + bv.x, acc[tm][j][3] + bv.y);
        }
    }
}

__device__ __forceinline__ float sig_t(float half_arg) {
    // sigmoid(2*half_arg) = 0.5*tanh(half_arg) + 0.5
    float t;
    asm("tanh.approx.f32 %0, %1;" : "=f"(t) : "f"(half_arg));
    return fmaf(0.5f, t, 0.5f);
}

// ---------------------------------------------------------------------------
// Warp per node: x_new[c] = x[c] + sum_e sigmoid(A[c]+B[s]) * x[s]
// ---------------------------------------------------------------------------
__global__ __launch_bounds__(256) void edge_agg_k(
    const float* __restrict__ x, const int* __restrict__ esrc)
{
    const int gw   = (blockIdx.x * 256 + threadIdx.x) >> 5;
    const int lane = threadIdx.x & 31;
    if (gw >= NN) return;
    const int c    = gw;
    const int s_my = esrc[c * DEG + (lane & 15)];

    const float4 a = ((const float4*)g_A)[(size_t)c * 32 + lane];
    const __half2 h05  = __floats2half2_rn(0.5f, 0.5f);
    const __half2 ha01 = __floats2half2_rn(0.5f * a.x, 0.5f * a.y);
    const __half2 ha23 = __floats2half2_rn(0.5f * a.z, 0.5f * a.w);

    float4 acc = make_float4(0.f, 0.f, 0.f, 0.f);

#pragma unroll
    for (int e = 0; e < DEG; e++) {
        const int   s = __shfl_sync(0xffffffffu, s_my, e);
        const uint4 p = g_bx[(size_t)s * 32 + lane];
        const __half2 b01 = *(const __half2*)&p.x;
        const __half2 b23 = *(const __half2*)&p.y;
        const float2 h01 = __half22float2(__hfma2(b01, h05, ha01));
        const float2 h23 = __half22float2(__hfma2(b23, h05, ha23));
        const float2 xf01 = __half22float2(*(const __half2*)&p.z);
        const float2 xf23 = __half22float2(*(const __half2*)&p.w);
        acc.x = fmaf(sig_t(h01.x), xf01.x, acc.x);
        acc.y = fmaf(sig_t(h01.y), xf01.y, acc.y);
        acc.z = fmaf(sig_t(h23.x), xf23.x, acc.z);
        acc.w = fmaf(sig_t(h23.y), xf23.y, acc.w);
    }

    const float4 xc = ((const float4*)x)[(size_t)c * 32 + lane];
    __half2 o01 = __floats2half2_rn(xc.x + acc.x, xc.y + acc.y);
    __half2 o23 = __floats2half2_rn(xc.z + acc.z, xc.w + acc.w);
    g_xnh[(size_t)c * 32 + lane] = make_uint2(*(uint32_t*)&o01, *(uint32_t*)&o23);
}

// ---------------------------------------------------------------------------
// Warp per node: g[c] = sum_e adj[e] * x_new_fp16[s_e]  (fp32 out)
// ---------------------------------------------------------------------------
__global__ __launch_bounds__(256) void gather_k(
    const float* __restrict__ adj, const int* __restrict__ esrc)
{
    const int gw   = (blockIdx.x * 256 + threadIdx.x) >> 5;
    const int lane = threadIdx.x & 31;
    if (gw >= NN) return;
    const int   c    = gw;
    const int   s_my = esrc[c * DEG + (lane & 15)];
    const float a_my = adj[c * DEG + (lane & 15)];

    float4 acc = make_float4(0.f, 0.f, 0.f, 0.f);

#pragma unroll
    for (int e = 0; e < DEG; e++) {
        const int   s  = __shfl_sync(0xffffffffu, s_my, e);
        const float av = __shfl_sync(0xffffffffu, a_my, e);
        const uint2 p  = g_xnh[(size_t)s * 32 + lane];
        const float2 v01 = __half22float2(*(const __half2*)&p.x);
        const float2 v23 = __half22float2(*(const __half2*)&p.y);
        acc.x = fmaf(av, v01.x, acc.x);
        acc.y = fmaf(av, v01.y, acc.y);
        acc.z = fmaf(av, v23.x, acc.z);
        acc.w = fmaf(av, v23.y, acc.w);
    }
    ((float4*)g_g)[(size_t)c * 32 + lane] = acc;
}

// ---------------------------------------------------------------------------
extern "C" void kernel_launch(void* const* d_in, const int* in_sizes, int n_in,
                              void* d_out, int out_size)
{
    const float* x      = (const float*)d_in[0];  // [N,128]
    const float* weight = (const float*)d_in[1];  // [128,128]
    const float* bias   = (const float*)d_in[2];  // [128]
    const float* wm     = (const float*)d_in[3];  // [256,128]
    const float* adj    = (const float*)d_in[4];  // [E]
    const int*   esrc   = (const int*)d_in[5];    // [E]
    float* out = (float*)d_out;

    void* pg;
    cudaGetSymbolAddress(&pg, g_g);

    cudaFuncSetAttribute(wm_merged_k, cudaFuncAttributeMaxDynamicSharedMemorySize,
                         WM_SMEM);
    cudaFuncSetAttribute(tc_gemm_k, cudaFuncAttributeMaxDynamicSharedMemorySize,
                         TC_SMEM);

    const int gemm_grid = (NN + 127) / 128;  // 391
    const int warp_grid = (NN + 7) / 8;      // 6250

    // A = x@Wm_top (fp32) and B = x@Wm_bot (fp16, packed) in one launch
    wm_merged_k<<<gemm_grid, 512, WM_SMEM>>>(x, wm, NN);

    // x_new (fp16) = x + sum_e sigmoid(A[c]+B[s]) * x[s]
    edge_agg_k<<<warp_grid, 256>>>(x, esrc);

    // g[c] = sum_e adj[e] * x_new[s]
    gather_k<<<warp_grid, 256>>>(adj, esrc);

    // out = g @ weight + bias
    tc_gemm_k<<<gemm_grid, 256, TC_SMEM>>>((const float*)pg, weight, bias, out, NN);
}